// round 3
// baseline (speedup 1.0000x reference)
#include <cuda_runtime.h>
#include <cuda_bf16.h>
#include <cstdint>

// Problem constants
#define NXg 512
#define NYg 512
#define NSENS 128
#define NT 2048
#define NPIX (NXg * NYg)

// Scratch: sensor data transposed to [s][t][8 channels] as 2x float4 per (s,t).
// 128 * 2048 * 8 floats = 8 MB (fits L2, 126 MB).
__device__ float4 g_scratch[NSENS * NT * 2];

// ---------------------------------------------------------------------------
// Prep kernel: transpose sensor_data [B=4][C=2][S=128][T=2048] -> [S][T][bc=8]
// ---------------------------------------------------------------------------
__global__ __launch_bounds__(256) void das_transpose_kernel(
    const float* __restrict__ sd)
{
    int idx = blockIdx.x * blockDim.x + threadIdx.x;   // 0 .. 128*2048-1
    if (idx >= NSENS * NT) return;
    int s = idx >> 11;          // sensor
    int t = idx & (NT - 1);     // time sample

    const int bcStride = NSENS * NT;                   // 262144 floats
    const float* base = sd + s * NT + t;

    float4 v0, v1;
    v0.x = base[0 * bcStride];
    v0.y = base[1 * bcStride];
    v0.z = base[2 * bcStride];
    v0.w = base[3 * bcStride];
    v1.x = base[4 * bcStride];
    v1.y = base[5 * bcStride];
    v1.z = base[6 * bcStride];
    v1.w = base[7 * bcStride];

    g_scratch[idx * 2 + 0] = v0;
    g_scratch[idx * 2 + 1] = v1;
}

// ---------------------------------------------------------------------------
// Main DAS kernel: one thread per pixel, loop over 128 sensors.
// Block = 16x16 pixel tile (tx = iy direction, ty = ix direction).
// ---------------------------------------------------------------------------
__global__ __launch_bounds__(256) void das_main_kernel(
    const int* __restrict__ sensor_xy,   // [128][2] int32
    float* __restrict__ out)             // [8][NPIX]
{
    __shared__ float2 sxy[NSENS];

    int tid = threadIdx.y * 16 + threadIdx.x;
    if (tid < NSENS) {
        int2 xy = ((const int2*)sensor_xy)[tid];
        sxy[tid] = make_float2((float)xy.x, (float)xy.y);
    }
    __syncthreads();

    int iy = blockIdx.x * 16 + threadIdx.x;   // fast dim (warp-contiguous)
    int ix = blockIdx.y * 16 + threadIdx.y;

    float fix = (float)ix;
    float fiy = (float)iy;

    float4 a0 = make_float4(0.f, 0.f, 0.f, 0.f);
    float4 a1 = make_float4(0.f, 0.f, 0.f, 0.f);

    // XLA chain (algebraic simplifier, post-order):
    //   dis / VS      -> dis * fl(1/VS)          (div-by-const -> mul-by-recip)
    //   (...) / DT    -> (...) * fl(1/DT)
    //   mul-mul merge -> dis * fl(fl(1/VS)*fl(1/DT))
    // All constant folding in IEEE fp32 RN, identical to nvcc's front-end
    // folding of these literals.
    const float K = (1.0f / 1550.0f) * (1.0f / 2.5e-8f);

    #pragma unroll 4
    for (int s = 0; s < NSENS; ++s) {
        float2 c = sxy[s];
        // (x - ix + 1 - 1) is exact integer arithmetic in fp32 (|val| <= 512)
        float dx = __fmul_rn(c.x - fix, 1e-4f);
        float dy = __fmul_rn(c.y - fiy, 1e-4f);
        float r2 = __fadd_rn(__fmul_rn(dx, dx), __fmul_rn(dy, dy));
        float dis = __fsqrt_rn(r2);
        int t = (int)__fmul_rn(dis, K);

        const float4* p4 = &g_scratch[(((unsigned)s << 11) + (unsigned)t) << 1];
        float4 v0 = __ldg(p4 + 0);
        float4 v1 = __ldg(p4 + 1);
        a0.x += v0.x; a0.y += v0.y; a0.z += v0.z; a0.w += v0.w;
        a1.x += v1.x; a1.y += v1.y; a1.z += v1.z; a1.w += v1.w;
    }

    int p = ix * NYg + iy;
    out[0 * NPIX + p] = a0.x;
    out[1 * NPIX + p] = a0.y;
    out[2 * NPIX + p] = a0.z;
    out[3 * NPIX + p] = a0.w;
    out[4 * NPIX + p] = a1.x;
    out[5 * NPIX + p] = a1.y;
    out[6 * NPIX + p] = a1.z;
    out[7 * NPIX + p] = a1.w;
}

// ---------------------------------------------------------------------------
// Entry point
// ---------------------------------------------------------------------------
extern "C" void kernel_launch(void* const* d_in, const int* in_sizes, int n_in,
                              void* d_out, int out_size)
{
    const float* sensor_data = (const float*)d_in[0];   // (4,2,128,2048) f32
    const int*   sensor_xy   = (const int*)d_in[1];     // (128,2) i32
    float*       out         = (float*)d_out;           // (4,2,512,512) f32

    // 1) transpose sensor data into channel-interleaved scratch
    das_transpose_kernel<<<(NSENS * NT + 255) / 256, 256>>>(sensor_data);

    // 2) delay-and-sum
    dim3 block(16, 16);
    dim3 grid(NYg / 16, NXg / 16);
    das_main_kernel<<<grid, block>>>(sensor_xy, out);
}